// round 2
// baseline (speedup 1.0000x reference)
#include <cuda_runtime.h>
#include <math.h>

#define DIM 128

// ---------------------------------------------------------------------------
// device scratch (allocation-free rule: __device__ globals)
// ---------------------------------------------------------------------------
__device__ int   g_is64;                 // 1 if idx tensors are int64
__device__ int   g_pi32[800000 + 64];    // canonical int32 path_idx
__device__ int   g_y32[4096];            // canonical int32 y
__device__ float g_row_loss[4096];
__device__ float g_fallback[57600000];   // logits+aw fallback if out layout差

// ---------------------------------------------------------------------------
// dtype detect: int64 little-endian values < 2^16 => odd 32-bit words all zero
// ---------------------------------------------------------------------------
__global__ void detect_kernel(const unsigned int* __restrict__ w) {
    if (threadIdx.x == 0) {
        int is64 = 1;
        #pragma unroll
        for (int i = 0; i < 32; ++i)
            if (w[2 * i + 1] != 0u) { is64 = 0; break; }
        g_is64 = is64;
    }
}

__global__ void convert_kernel(const void* __restrict__ pi_raw,
                               const void* __restrict__ y_raw,
                               int nPI, int nY) {
    const int is64 = g_is64;
    int i = blockIdx.x * blockDim.x + threadIdx.x;
    if (i < nPI) {
        g_pi32[i] = is64 ? (int)((const long long*)pi_raw)[i]
                         : ((const int*)pi_raw)[i];
    }
    if (i < nY) {
        g_y32[i] = is64 ? (int)((const long long*)y_raw)[i]
                        : ((const int*)y_raw)[i];
    }
}

// ---------------------------------------------------------------------------
// Kernel A: added_weights[k] = weights[k] + sum_{p<len[k]} weights[path_idx[k][p]]
// one block per class, 128 threads (one per dim); gathers mostly hit L2.
// ---------------------------------------------------------------------------
__global__ void aw_kernel(const float* __restrict__ weights,
                          const int* __restrict__ path_len,
                          float* __restrict__ aw, int K, int Dmax) {
    int k = blockIdx.x;
    if (k >= K) return;
    int d = threadIdx.x;
    float s = weights[(size_t)k * DIM + d];
    int len = path_len[k];
    const int* pk = g_pi32 + (size_t)k * Dmax;
    for (int p = 0; p < len; ++p) {
        int idx = pk[p];
        s += weights[(size_t)idx * DIM + d];
    }
    aw[(size_t)k * DIM + d] = s;
}

// ---------------------------------------------------------------------------
// Kernel B: logits = x @ aw^T  (fp32 SGEMM, 128x128 block tile, 8x8 micro)
// ---------------------------------------------------------------------------
#define BM 128
#define BN 128
#define BD 16
#define TM 8
#define TN 8
#define PAD 4

__global__ __launch_bounds__(256, 2)
void gemm_kernel(const float* __restrict__ X,   // [B, 128]
                 const float* __restrict__ W,   // [K, 128]
                 float* __restrict__ out,       // [B, K]
                 int B, int K) {
    __shared__ float As[BD][BM + PAD];
    __shared__ float Ws[BD][BN + PAD];

    const int bm = blockIdx.y * BM;
    const int bn = blockIdx.x * BN;
    const int tid = threadIdx.x;
    const int tx = tid % 16;
    const int ty = tid / 16;

    float acc[TM][TN];
    #pragma unroll
    for (int i = 0; i < TM; ++i)
        #pragma unroll
        for (int j = 0; j < TN; ++j) acc[i][j] = 0.0f;

    for (int d0 = 0; d0 < DIM; d0 += BD) {
        #pragma unroll
        for (int i = 0; i < 8; ++i) {
            int e = tid + i * 256;
            int row = e >> 4;
            int col = e & 15;
            int m = bm + row;
            As[col][row] = (m < B) ? X[(size_t)m * DIM + d0 + col] : 0.0f;
        }
        #pragma unroll
        for (int i = 0; i < 8; ++i) {
            int e = tid + i * 256;
            int row = e >> 4;
            int col = e & 15;
            int k = bn + row;
            Ws[col][row] = (k < K) ? W[(size_t)k * DIM + d0 + col] : 0.0f;
        }
        __syncthreads();

        #pragma unroll
        for (int d = 0; d < BD; ++d) {
            const float4* ap = reinterpret_cast<const float4*>(&As[d][ty * TM]);
            const float4* bp = reinterpret_cast<const float4*>(&Ws[d][tx * TN]);
            float4 a0 = ap[0], a1 = ap[1];
            float4 b0 = bp[0], b1 = bp[1];
            float a[TM] = {a0.x, a0.y, a0.z, a0.w, a1.x, a1.y, a1.z, a1.w};
            float b[TN] = {b0.x, b0.y, b0.z, b0.w, b1.x, b1.y, b1.z, b1.w};
            #pragma unroll
            for (int i = 0; i < TM; ++i)
                #pragma unroll
                for (int j = 0; j < TN; ++j)
                    acc[i][j] = fmaf(a[i], b[j], acc[i][j]);
        }
        __syncthreads();
    }

    #pragma unroll
    for (int i = 0; i < TM; ++i) {
        int row = bm + ty * TM + i;
        if (row >= B) continue;
        size_t base = (size_t)row * K;
        #pragma unroll
        for (int j = 0; j < TN; ++j) {
            int k = bn + tx * TN + j;
            if (k < K) out[base + k] = acc[i][j];
        }
    }
}

// ---------------------------------------------------------------------------
// Kernel C: per-row logsumexp with thresholded exp; row_loss = lse - logit[y]
// ---------------------------------------------------------------------------
__global__ void lse_kernel(const float* __restrict__ logits,
                           int B, int K) {
    int b = blockIdx.x;
    if (b >= B) return;
    const float* row = logits + (size_t)b * K;
    int tid = threadIdx.x;
    const int NT = blockDim.x;

    __shared__ float sm[256];

    float m = -INFINITY;
    for (int i = tid; i < K; i += NT) m = fmaxf(m, row[i]);
    sm[tid] = m;
    __syncthreads();
    for (int s = 128; s > 0; s >>= 1) {
        if (tid < s) sm[tid] = fmaxf(sm[tid], sm[tid + s]);
        __syncthreads();
    }
    m = sm[0];
    __syncthreads();

    float thr = m - 30.0f;
    float s = 0.0f;
    for (int i = tid; i < K; i += NT) {
        float v = row[i];
        if (v > thr) s += expf(v - m);
    }
    sm[tid] = s;
    __syncthreads();
    for (int k = 128; k > 0; k >>= 1) {
        if (tid < k) sm[tid] += sm[tid + k];
        __syncthreads();
    }
    if (tid == 0) {
        float lse = m + logf(sm[0]);
        g_row_loss[b] = lse - row[g_y32[b]];
    }
}

__global__ void loss_kernel(float* __restrict__ out, int B) {
    __shared__ float sm[256];
    int tid = threadIdx.x;
    float s = 0.0f;
    for (int i = tid; i < B; i += 256) s += g_row_loss[i];
    sm[tid] = s;
    __syncthreads();
    for (int k = 128; k > 0; k >>= 1) {
        if (tid < k) sm[tid] += sm[tid + k];
        __syncthreads();
    }
    if (tid == 0) out[0] = sm[0] / (float)B;
}

// ---------------------------------------------------------------------------
// Launch. Inputs identified BY SIZE (immune to ordering):
//   weights 8,388,608 > path_idx 800,000 > x 131,072 > path_len 50,000 > y 1,024
// ---------------------------------------------------------------------------
extern "C" void kernel_launch(void* const* d_in, const int* in_sizes, int n_in,
                              void* d_out, int out_size) {
    // rank inputs by element count
    const void* weights_p = nullptr; int weights_n = -1;
    const void* pi_p = nullptr;      int pi_n = -1;
    const void* x_p = nullptr;       int x_n = -1;
    const void* pl_p = nullptr;      int pl_n = -1;
    const void* y_p = nullptr;       int y_n = -1;

    // simple selection over n_in entries: sort indices by size descending
    int order[16];
    for (int i = 0; i < n_in; ++i) order[i] = i;
    for (int i = 0; i < n_in; ++i)
        for (int j = i + 1; j < n_in; ++j)
            if (in_sizes[order[j]] > in_sizes[order[i]]) {
                int t = order[i]; order[i] = order[j]; order[j] = t;
            }
    weights_p = d_in[order[0]]; weights_n = in_sizes[order[0]];
    pi_p      = d_in[order[1]]; pi_n      = in_sizes[order[1]];
    x_p       = d_in[order[2]]; x_n       = in_sizes[order[2]];
    pl_p      = d_in[order[3]]; pl_n      = in_sizes[order[3]];
    y_p       = d_in[order[4]]; y_n       = in_sizes[order[4]];

    const float* weights  = (const float*)weights_p;
    const float* x        = (const float*)x_p;
    const int*   path_len = (const int*)pl_p;

    const int K    = pl_n;          // 50000
    const int B    = y_n;           // 1024
    const int Dmax = pi_n / K;      // 16

    // output layout: [loss][logits B*K][added_weights K*128] if it fits,
    // else device-scratch fallback (only loss written to d_out)
    float* out = (float*)d_out;
    size_t expected = 1 + (size_t)B * K + (size_t)K * DIM;
    float* loss;
    float* logits;
    float* aw;
    if ((size_t)out_size >= expected) {
        loss   = out;
        logits = out + 1;
        aw     = out + 1 + (size_t)B * K;
    } else {
        loss   = out;
        logits = g_fallback;
        aw     = g_fallback + (size_t)B * K;
    }

    // 1) dtype detect + canonicalize indices
    detect_kernel<<<1, 32>>>((const unsigned int*)pi_p);
    int nconv = pi_n > B ? pi_n : B;
    convert_kernel<<<(nconv + 255) / 256, 256>>>(pi_p, y_p, pi_n, B);

    // 2) added_weights gather-sum
    aw_kernel<<<K, 128>>>(weights, path_len, aw, K, Dmax);

    // 3) logits SGEMM
    dim3 grid((K + BN - 1) / BN, (B + BM - 1) / BM);
    gemm_kernel<<<grid, 256>>>(x, aw, logits, B, K);

    // 4) per-row loss + mean
    lse_kernel<<<B, 256>>>(logits, B, K);
    loss_kernel<<<1, 256>>>(loss, B);
}

// round 4
// speedup vs baseline: 2.0722x; 2.0722x over previous
#include <cuda_runtime.h>
#include <cuda_bf16.h>
#include <math.h>
#include <stdint.h>

#define DIM 128

// ---------------------------------------------------------------------------
// device scratch (allocation-free: __device__ globals)
// ---------------------------------------------------------------------------
__device__ int      g_is64;
__device__ int      g_pi32[800000 + 64];
__device__ int      g_y32[4096];
__device__ float    g_row_loss[4096];
__device__ unsigned g_rowmax_u[4096];
__device__ __nv_bfloat16 g_bh[51200 * 128];   // added_weights hi (padded rows)
__device__ __nv_bfloat16 g_bl[51200 * 128];   // added_weights lo
__device__ __nv_bfloat16 g_xh[2048 * 128];    // x hi (padded rows)
__device__ __nv_bfloat16 g_xl[2048 * 128];    // x lo

// ---------------------------------------------------------------------------
// helpers
// ---------------------------------------------------------------------------
__device__ __forceinline__ unsigned f2mono(float f) {
    unsigned u = __float_as_uint(f);
    return (u & 0x80000000u) ? ~u : (u | 0x80000000u);
}
__device__ __forceinline__ float mono2f(unsigned m) {
    unsigned u = (m & 0x80000000u) ? (m & 0x7FFFFFFFu) : ~m;
    return __uint_as_float(u);
}
__device__ __forceinline__ uint32_t smem_u32(const void* p) {
    uint32_t a;
    asm("{ .reg .u64 t; cvta.to.shared.u64 t, %1; cvt.u32.u64 %0, t; }" : "=r"(a) : "l"(p));
    return a;
}

#define LDMX4(r0, r1, r2, r3, addr) \
    asm volatile("ldmatrix.sync.aligned.m8n8.x4.shared.b16 {%0,%1,%2,%3}, [%4];" \
                 : "=r"(r0), "=r"(r1), "=r"(r2), "=r"(r3) : "r"(addr))

#define MMA16816(c0, c1, c2, c3, a0, a1, a2, a3, b0, b1) \
    asm volatile("mma.sync.aligned.m16n8k16.row.col.f32.bf16.bf16.f32 " \
                 "{%0,%1,%2,%3}, {%4,%5,%6,%7}, {%8,%9}, {%0,%1,%2,%3};" \
                 : "+f"(c0), "+f"(c1), "+f"(c2), "+f"(c3) \
                 : "r"(a0), "r"(a1), "r"(a2), "r"(a3), "r"(b0), "r"(b1))

// ---------------------------------------------------------------------------
// dtype detect + index canonicalization
// ---------------------------------------------------------------------------
__global__ void detect_kernel(const unsigned int* __restrict__ w) {
    if (threadIdx.x == 0) {
        int is64 = 1;
        #pragma unroll
        for (int i = 0; i < 32; ++i)
            if (w[2 * i + 1] != 0u) { is64 = 0; break; }
        g_is64 = is64;
    }
}
__global__ void convert_kernel(const void* __restrict__ pi_raw,
                               const void* __restrict__ y_raw, int nPI, int nY) {
    const int is64 = g_is64;
    int i = blockIdx.x * blockDim.x + threadIdx.x;
    if (i < nPI)
        g_pi32[i] = is64 ? (int)((const long long*)pi_raw)[i] : ((const int*)pi_raw)[i];
    if (i < nY)
        g_y32[i] = is64 ? (int)((const long long*)y_raw)[i] : ((const int*)y_raw)[i];
}
__global__ void init_kernel(int B) {
    int i = blockIdx.x * blockDim.x + threadIdx.x;
    if (i < B) g_rowmax_u[i] = 0u;
}

// ---------------------------------------------------------------------------
// aw: fp32 added_weights (exact) + bf16 hi/lo row-major
// ---------------------------------------------------------------------------
__global__ void aw_kernel(const float* __restrict__ weights,
                          const int* __restrict__ path_len,
                          float* __restrict__ aw, int K, int Dmax) {
    int k = blockIdx.x;
    int d = threadIdx.x;
    float s = 0.0f;
    if (k < K) {
        s = weights[(size_t)k * DIM + d];
        int len = path_len[k];
        const int* pk = g_pi32 + (size_t)k * Dmax;
        for (int p = 0; p < len; ++p)
            s += weights[(size_t)pk[p] * DIM + d];
        aw[(size_t)k * DIM + d] = s;
    }
    __nv_bfloat16 h = __float2bfloat16(s);
    __nv_bfloat16 l = __float2bfloat16(s - __bfloat162float(h));
    g_bh[(size_t)k * DIM + d] = h;
    g_bl[(size_t)k * DIM + d] = l;
}

__global__ void xconv_kernel(const float* __restrict__ x, int B) {
    int r = blockIdx.x;
    int d = threadIdx.x;
    float v = (r < B) ? x[(size_t)r * DIM + d] : 0.0f;
    __nv_bfloat16 h = __float2bfloat16(v);
    __nv_bfloat16 l = __float2bfloat16(v - __bfloat162float(h));
    g_xh[(size_t)r * DIM + d] = h;
    g_xl[(size_t)r * DIM + d] = l;
}

// ---------------------------------------------------------------------------
// bf16x3 HMMA GEMM: logits = x @ aw^T
// CTA = 128x128 tile; 8 warps, warp tile 64(M) x 32(N); K=128 resident.
// SMEM rows padded to 136 bf16 (272 B) for conflict-free ldmatrix.
// ---------------------------------------------------------------------------
#define ROWB 272                       // bytes per padded smem row
#define SZ_T (128 * ROWB)              // one 128x128 bf16 tile in smem (34816 B)
#define OFF_AH 0
#define OFF_AL (SZ_T)
#define OFF_BH (2 * SZ_T)
#define OFF_BL (3 * SZ_T)
#define SMEM_TOTAL (4 * SZ_T)

__global__ void __launch_bounds__(256, 1)
gemm_kernel(float* __restrict__ logits, int B, int K, int mtiles) {
    extern __shared__ char smem[];
    const uint32_t sb = smem_u32(smem);
    const int tid  = threadIdx.x;
    const int lane = tid & 31;
    const int wid  = tid >> 5;
    const int wm   = wid >> 2;          // 0..1 (64 rows)
    const int wn   = wid & 3;           // 0..3 (32 cols)
    const int nbase = blockIdx.x * 128;

    // copy B tile (hi+lo), resident for all m-iters
    {
        const uint4* sh = (const uint4*)(g_bh + (size_t)nbase * DIM);
        const uint4* sl = (const uint4*)(g_bl + (size_t)nbase * DIM);
        #pragma unroll
        for (int i = 0; i < 8; ++i) {
            int idx = tid + i * 256;            // 0..2047
            int row = idx >> 4, q = idx & 15;
            *(uint4*)(smem + OFF_BH + row * ROWB + q * 16) = sh[idx];
            *(uint4*)(smem + OFF_BL + row * ROWB + q * 16) = sl[idx];
        }
    }

    // precomputed ldmatrix lane addresses (offsets within a tile)
    const uint32_t a_row = (uint32_t)(wm * 64 + (lane & 15));
    const uint32_t a_kh  = (uint32_t)((lane >> 4) * 8);
    const uint32_t b_row0 = (uint32_t)(wn * 32 + ((lane >> 4) & 1) * 8 + (lane & 7));
    const uint32_t b_kh   = (uint32_t)(((lane >> 3) & 1) * 8);

    for (int m = 0; m < mtiles; ++m) {
        // copy A tile (hi+lo) for this m
        {
            const uint4* sh = (const uint4*)(g_xh + (size_t)m * 128 * DIM);
            const uint4* sl = (const uint4*)(g_xl + (size_t)m * 128 * DIM);
            #pragma unroll
            for (int i = 0; i < 8; ++i) {
                int idx = tid + i * 256;
                int row = idx >> 4, q = idx & 15;
                *(uint4*)(smem + OFF_AH + row * ROWB + q * 16) = sh[idx];
                *(uint4*)(smem + OFF_AL + row * ROWB + q * 16) = sl[idx];
            }
        }
        __syncthreads();

        float acc[4][4][4];
        #pragma unroll
        for (int i = 0; i < 4; ++i)
            #pragma unroll
            for (int j = 0; j < 4; ++j)
                #pragma unroll
                for (int e = 0; e < 4; ++e) acc[i][j][e] = 0.0f;

        #pragma unroll
        for (int pass = 0; pass < 3; ++pass) {
            const uint32_t abase = sb + ((pass == 2) ? OFF_AL : OFF_AH);
            const uint32_t bbase = sb + ((pass == 1) ? OFF_BL : OFF_BH);
            #pragma unroll
            for (int ks = 0; ks < 8; ++ks) {
                uint32_t af[4][4];
                #pragma unroll
                for (int mt = 0; mt < 4; ++mt) {
                    uint32_t addr = abase + (a_row + mt * 16) * ROWB
                                  + (ks * 16 + a_kh) * 2;
                    LDMX4(af[mt][0], af[mt][1], af[mt][2], af[mt][3], addr);
                }
                uint32_t bfr[4][2];
                #pragma unroll
                for (int half = 0; half < 2; ++half) {
                    uint32_t addr = bbase + (b_row0 + half * 16) * ROWB
                                  + (ks * 16 + b_kh) * 2;
                    uint32_t r0, r1, r2, r3;
                    LDMX4(r0, r1, r2, r3, addr);
                    bfr[2 * half][0] = r0; bfr[2 * half][1] = r1;
                    bfr[2 * half + 1][0] = r2; bfr[2 * half + 1][1] = r3;
                }
                #pragma unroll
                for (int mt = 0; mt < 4; ++mt)
                    #pragma unroll
                    for (int nt = 0; nt < 4; ++nt)
                        MMA16816(acc[mt][nt][0], acc[mt][nt][1],
                                 acc[mt][nt][2], acc[mt][nt][3],
                                 af[mt][0], af[mt][1], af[mt][2], af[mt][3],
                                 bfr[nt][0], bfr[nt][1]);
            }
        }

        // epilogue: store + fused row max
        const int ncol = nbase + wn * 32 + (lane & 3) * 2;
        #pragma unroll
        for (int mt = 0; mt < 4; ++mt) {
            #pragma unroll
            for (int h = 0; h < 2; ++h) {
                int gr = m * 128 + wm * 64 + mt * 16 + h * 8 + (lane >> 2);
                if (gr < B) {
                    size_t base = (size_t)gr * K;
                    float rmax = -INFINITY;
                    #pragma unroll
                    for (int nt = 0; nt < 4; ++nt) {
                        int n = ncol + nt * 8;
                        float v0 = acc[mt][nt][2 * h];
                        float v1 = acc[mt][nt][2 * h + 1];
                        if (n < K)     { logits[base + n] = v0;     rmax = fmaxf(rmax, v0); }
                        if (n + 1 < K) { logits[base + n + 1] = v1; rmax = fmaxf(rmax, v1); }
                    }
                    rmax = fmaxf(rmax, __shfl_xor_sync(0xFFFFFFFFu, rmax, 1));
                    rmax = fmaxf(rmax, __shfl_xor_sync(0xFFFFFFFFu, rmax, 2));
                    if ((lane & 3) == 0)
                        atomicMax(&g_rowmax_u[gr], f2mono(rmax));
                }
            }
        }
        __syncthreads();
    }
}

// ---------------------------------------------------------------------------
// single-pass thresholded logsumexp using precomputed row max
// ---------------------------------------------------------------------------
__global__ void lse_kernel(const float* __restrict__ logits, int B, int K) {
    int b = blockIdx.x;
    if (b >= B) return;
    const float* row = logits + (size_t)b * K;
    int tid = threadIdx.x;
    __shared__ float sm[256];

    float m = mono2f(g_rowmax_u[b]);
    float thr = m - 30.0f;
    float s = 0.0f;
    for (int i = tid; i < K; i += 256) {
        float v = row[i];
        if (v > thr) s += expf(v - m);
    }
    sm[tid] = s;
    __syncthreads();
    for (int k = 128; k > 0; k >>= 1) {
        if (tid < k) sm[tid] += sm[tid + k];
        __syncthreads();
    }
    if (tid == 0) {
        float lse = m + logf(sm[0]);
        g_row_loss[b] = lse - row[g_y32[b]];
    }
}

__global__ void loss_kernel(float* __restrict__ out, int B) {
    __shared__ float sm[256];
    int tid = threadIdx.x;
    float s = 0.0f;
    for (int i = tid; i < B; i += 256) s += g_row_loss[i];
    sm[tid] = s;
    __syncthreads();
    for (int k = 128; k > 0; k >>= 1) {
        if (tid < k) sm[tid] += sm[tid + k];
        __syncthreads();
    }
    if (tid == 0) out[0] = sm[0] / (float)B;
}

// ---------------------------------------------------------------------------
// launch — inputs identified by element count
// ---------------------------------------------------------------------------
extern "C" void kernel_launch(void* const* d_in, const int* in_sizes, int n_in,
                              void* d_out, int out_size) {
    int order[16];
    for (int i = 0; i < n_in; ++i) order[i] = i;
    for (int i = 0; i < n_in; ++i)
        for (int j = i + 1; j < n_in; ++j)
            if (in_sizes[order[j]] > in_sizes[order[i]]) {
                int t = order[i]; order[i] = order[j]; order[j] = t;
            }
    const float* weights  = (const float*)d_in[order[0]];
    const void*  pi_p     = d_in[order[1]];
    const float* x        = (const float*)d_in[order[2]];
    const int*   path_len = (const int*)d_in[order[3]];
    const void*  y_p      = d_in[order[4]];

    const int pi_n = in_sizes[order[1]];
    const int K    = in_sizes[order[3]];
    const int B    = in_sizes[order[4]];
    const int Dmax = pi_n / K;

    const int ntiles = (K + 127) / 128;
    const int mtiles = (B + 127) / 128;

    float* out    = (float*)d_out;
    float* loss   = out;
    float* logits = out + 1;
    float* aw     = out + 1 + (size_t)B * K;

    cudaFuncSetAttribute(gemm_kernel, cudaFuncAttributeMaxDynamicSharedMemorySize, SMEM_TOTAL);

    init_kernel<<<(B + 255) / 256, 256>>>(B);
    detect_kernel<<<1, 32>>>((const unsigned int*)pi_p);
    int nconv = pi_n > B ? pi_n : B;
    convert_kernel<<<(nconv + 255) / 256, 256>>>(pi_p, y_p, pi_n, B);

    xconv_kernel<<<mtiles * 128, 128>>>(x, B);
    aw_kernel<<<ntiles * 128, 128>>>(weights, path_len, aw, K, Dmax);

    gemm_kernel<<<ntiles, 256, SMEM_TOTAL>>>(logits, B, K, mtiles);

    lse_kernel<<<B, 256>>>(logits, B, K);
    loss_kernel<<<1, 256>>>(loss, B);
}

// round 5
// speedup vs baseline: 2.4002x; 1.1583x over previous
#include <cuda_runtime.h>
#include <cuda_bf16.h>
#include <math.h>
#include <stdint.h>

#define DIM 128

// ---------------------------------------------------------------------------
// device scratch (allocation-free: __device__ globals)
// ---------------------------------------------------------------------------
__device__ int      g_is64;
__device__ int      g_pi32[800000 + 64];
__device__ int      g_y32[4096];
__device__ float    g_row_loss[4096];
__device__ unsigned g_rowmax_u[4096];
__device__ __nv_bfloat16 g_bh[51200 * 128];
__device__ __nv_bfloat16 g_bl[51200 * 128];
__device__ __nv_bfloat16 g_xh[2048 * 128];
__device__ __nv_bfloat16 g_xl[2048 * 128];

// ---------------------------------------------------------------------------
// helpers
// ---------------------------------------------------------------------------
__device__ __forceinline__ unsigned f2mono(float f) {
    unsigned u = __float_as_uint(f);
    return (u & 0x80000000u) ? ~u : (u | 0x80000000u);
}
__device__ __forceinline__ float mono2f(unsigned m) {
    unsigned u = (m & 0x80000000u) ? (m & 0x7FFFFFFFu) : ~m;
    return __uint_as_float(u);
}
__device__ __forceinline__ uint32_t smem_u32(const void* p) {
    uint32_t a;
    asm("{ .reg .u64 t; cvta.to.shared.u64 t, %1; cvt.u32.u64 %0, t; }" : "=r"(a) : "l"(p));
    return a;
}

#define LDMX4(r0, r1, r2, r3, addr) \
    asm volatile("ldmatrix.sync.aligned.m8n8.x4.shared.b16 {%0,%1,%2,%3}, [%4];" \
                 : "=r"(r0), "=r"(r1), "=r"(r2), "=r"(r3) : "r"(addr))

#define MMA16816(c0, c1, c2, c3, a0, a1, a2, a3, b0, b1) \
    asm volatile("mma.sync.aligned.m16n8k16.row.col.f32.bf16.bf16.f32 " \
                 "{%0,%1,%2,%3}, {%4,%5,%6,%7}, {%8,%9}, {%0,%1,%2,%3};" \
                 : "+f"(c0), "+f"(c1), "+f"(c2), "+f"(c3) \
                 : "r"(a0), "r"(a1), "r"(a2), "r"(a3), "r"(b0), "r"(b1))

#define CPASYNC16(saddr, gptr) \
    asm volatile("cp.async.cg.shared.global [%0], [%1], 16;" :: "r"(saddr), "l"(gptr))
#define CPCOMMIT() asm volatile("cp.async.commit_group;" ::: "memory")
#define CPWAIT1()  asm volatile("cp.async.wait_group 1;" ::: "memory")
#define CPWAIT0()  asm volatile("cp.async.wait_group 0;" ::: "memory")

// ---------------------------------------------------------------------------
// dtype detect + index canonicalization
// ---------------------------------------------------------------------------
__global__ void detect_kernel(const unsigned int* __restrict__ w) {
    if (threadIdx.x == 0) {
        int is64 = 1;
        #pragma unroll
        for (int i = 0; i < 32; ++i)
            if (w[2 * i + 1] != 0u) { is64 = 0; break; }
        g_is64 = is64;
    }
}
__global__ void convert_kernel(const void* __restrict__ pi_raw,
                               const void* __restrict__ y_raw, int nPI, int nY) {
    const int is64 = g_is64;
    int i = blockIdx.x * blockDim.x + threadIdx.x;
    if (i < nPI)
        g_pi32[i] = is64 ? (int)((const long long*)pi_raw)[i] : ((const int*)pi_raw)[i];
    if (i < nY)
        g_y32[i] = is64 ? (int)((const long long*)y_raw)[i] : ((const int*)y_raw)[i];
}
__global__ void init_kernel(int B) {
    int i = blockIdx.x * blockDim.x + threadIdx.x;
    if (i < B) g_rowmax_u[i] = 0u;
}

// ---------------------------------------------------------------------------
// aw: fp32 added_weights (exact) + bf16 hi/lo row-major
// ---------------------------------------------------------------------------
__global__ void aw_kernel(const float* __restrict__ weights,
                          const int* __restrict__ path_len,
                          float* __restrict__ aw, int K, int Dmax) {
    int k = blockIdx.x;
    int d = threadIdx.x;
    float s = 0.0f;
    if (k < K) {
        s = weights[(size_t)k * DIM + d];
        int len = path_len[k];
        const int* pk = g_pi32 + (size_t)k * Dmax;
        for (int p = 0; p < len; ++p)
            s += weights[(size_t)pk[p] * DIM + d];
        aw[(size_t)k * DIM + d] = s;
    }
    __nv_bfloat16 h = __float2bfloat16(s);
    __nv_bfloat16 l = __float2bfloat16(s - __bfloat162float(h));
    g_bh[(size_t)k * DIM + d] = h;
    g_bl[(size_t)k * DIM + d] = l;
}

__global__ void xconv_kernel(const float* __restrict__ x, int B) {
    int r = blockIdx.x;
    int d = threadIdx.x;
    float v = (r < B) ? x[(size_t)r * DIM + d] : 0.0f;
    __nv_bfloat16 h = __float2bfloat16(v);
    __nv_bfloat16 l = __float2bfloat16(v - __bfloat162float(h));
    g_xh[(size_t)r * DIM + d] = h;
    g_xl[(size_t)r * DIM + d] = l;
}

// ---------------------------------------------------------------------------
// bf16x3 HMMA GEMM, fused single k-loop (acc += Ah*Bh + Ah*Bl + Al*Bh),
// cp.async double-buffered A tiles, B resident.
// SMEM: Bh|Bl (69.6KB) + A[2][hi|lo] (139KB) = 204KB
// ---------------------------------------------------------------------------
#define ROWB 272
#define SZ_T (128 * ROWB)
#define OFF_BH 0
#define OFF_BL (SZ_T)
#define OFF_A(buf, hl) (2 * SZ_T + (buf) * 2 * SZ_T + (hl) * SZ_T)
#define SMEM_TOTAL (6 * SZ_T)

__global__ void __launch_bounds__(256, 1)
gemm_kernel(float* __restrict__ logits, int B, int K, int mtiles) {
    extern __shared__ char smem[];
    const uint32_t sb = smem_u32(smem);
    const int tid  = threadIdx.x;
    const int lane = tid & 31;
    const int wid  = tid >> 5;
    const int wm   = wid >> 2;          // 0..1
    const int wn   = wid & 3;           // 0..3
    const int nbase = blockIdx.x * 128;

    // B tile copy via cp.async (one-time)
    {
        const char* sh = (const char*)(g_bh + (size_t)nbase * DIM);
        const char* sl = (const char*)(g_bl + (size_t)nbase * DIM);
        #pragma unroll
        for (int i = 0; i < 8; ++i) {
            int idx = tid + i * 256;
            int row = idx >> 4, q = idx & 15;
            CPASYNC16(sb + OFF_BH + row * ROWB + q * 16, sh + idx * 16);
            CPASYNC16(sb + OFF_BL + row * ROWB + q * 16, sl + idx * 16);
        }
        CPCOMMIT();
    }
    // prefetch A tile 0 into buf 0
    {
        const char* sh = (const char*)g_xh;
        const char* sl = (const char*)g_xl;
        #pragma unroll
        for (int i = 0; i < 8; ++i) {
            int idx = tid + i * 256;
            int row = idx >> 4, q = idx & 15;
            CPASYNC16(sb + OFF_A(0, 0) + row * ROWB + q * 16, sh + idx * 16);
            CPASYNC16(sb + OFF_A(0, 1) + row * ROWB + q * 16, sl + idx * 16);
        }
        CPCOMMIT();
    }

    const uint32_t a_row  = (uint32_t)(wm * 64 + (lane & 15));
    const uint32_t a_kh   = (uint32_t)((lane >> 4) * 8);
    const uint32_t b_row0 = (uint32_t)(wn * 32 + ((lane >> 4) & 1) * 8 + (lane & 7));
    const uint32_t b_kh   = (uint32_t)(((lane >> 3) & 1) * 8);

    for (int m = 0; m < mtiles; ++m) {
        // prefetch A[m+1] into buf (m+1)&1  (that buffer was last read at iter m-1)
        if (m + 1 < mtiles) {
            const char* sh = (const char*)(g_xh + (size_t)(m + 1) * 128 * DIM);
            const char* sl = (const char*)(g_xl + (size_t)(m + 1) * 128 * DIM);
            const int nb = (m + 1) & 1;
            #pragma unroll
            for (int i = 0; i < 8; ++i) {
                int idx = tid + i * 256;
                int row = idx >> 4, q = idx & 15;
                CPASYNC16(sb + OFF_A(nb, 0) + row * ROWB + q * 16, sh + idx * 16);
                CPASYNC16(sb + OFF_A(nb, 1) + row * ROWB + q * 16, sl + idx * 16);
            }
            CPCOMMIT();
            CPWAIT1();       // current buffer (and B) complete
        } else {
            CPWAIT0();
        }
        __syncthreads();

        const uint32_t ah_base = sb + OFF_A(m & 1, 0);
        const uint32_t al_base = sb + OFF_A(m & 1, 1);
        const uint32_t bh_base = sb + OFF_BH;
        const uint32_t bl_base = sb + OFF_BL;

        float acc[4][4][4];
        #pragma unroll
        for (int i = 0; i < 4; ++i)
            #pragma unroll
            for (int j = 0; j < 4; ++j)
                #pragma unroll
                for (int e = 0; e < 4; ++e) acc[i][j][e] = 0.0f;

        #pragma unroll
        for (int ks = 0; ks < 8; ++ks) {
            const uint32_t koff = (ks * 16) * 2;
            uint32_t ah[4][4], al[4][4];
            #pragma unroll
            for (int mt = 0; mt < 4; ++mt) {
                uint32_t ra = (a_row + mt * 16) * ROWB + koff + a_kh * 2;
                LDMX4(ah[mt][0], ah[mt][1], ah[mt][2], ah[mt][3], ah_base + ra);
                LDMX4(al[mt][0], al[mt][1], al[mt][2], al[mt][3], al_base + ra);
            }
            uint32_t bh[4][2], bl[4][2];
            #pragma unroll
            for (int half = 0; half < 2; ++half) {
                uint32_t rb = (b_row0 + half * 16) * ROWB + koff + b_kh * 2;
                uint32_t r0, r1, r2, r3;
                LDMX4(r0, r1, r2, r3, bh_base + rb);
                bh[2 * half][0] = r0; bh[2 * half][1] = r1;
                bh[2 * half + 1][0] = r2; bh[2 * half + 1][1] = r3;
                LDMX4(r0, r1, r2, r3, bl_base + rb);
                bl[2 * half][0] = r0; bl[2 * half][1] = r1;
                bl[2 * half + 1][0] = r2; bl[2 * half + 1][1] = r3;
            }
            // product 1: Ah*Bh
            #pragma unroll
            for (int mt = 0; mt < 4; ++mt)
                #pragma unroll
                for (int nt = 0; nt < 4; ++nt)
                    MMA16816(acc[mt][nt][0], acc[mt][nt][1], acc[mt][nt][2], acc[mt][nt][3],
                             ah[mt][0], ah[mt][1], ah[mt][2], ah[mt][3],
                             bh[nt][0], bh[nt][1]);
            // product 2: Ah*Bl
            #pragma unroll
            for (int mt = 0; mt < 4; ++mt)
                #pragma unroll
                for (int nt = 0; nt < 4; ++nt)
                    MMA16816(acc[mt][nt][0], acc[mt][nt][1], acc[mt][nt][2], acc[mt][nt][3],
                             ah[mt][0], ah[mt][1], ah[mt][2], ah[mt][3],
                             bl[nt][0], bl[nt][1]);
            // product 3: Al*Bh
            #pragma unroll
            for (int mt = 0; mt < 4; ++mt)
                #pragma unroll
                for (int nt = 0; nt < 4; ++nt)
                    MMA16816(acc[mt][nt][0], acc[mt][nt][1], acc[mt][nt][2], acc[mt][nt][3],
                             al[mt][0], al[mt][1], al[mt][2], al[mt][3],
                             bh[nt][0], bh[nt][1]);
        }

        // epilogue: direct stores + fused row max
        const int ncol = nbase + wn * 32 + (lane & 3) * 2;
        #pragma unroll
        for (int mt = 0; mt < 4; ++mt) {
            #pragma unroll
            for (int h = 0; h < 2; ++h) {
                int gr = m * 128 + wm * 64 + mt * 16 + h * 8 + (lane >> 2);
                if (gr < B) {
                    size_t base = (size_t)gr * K;
                    float rmax = -INFINITY;
                    #pragma unroll
                    for (int nt = 0; nt < 4; ++nt) {
                        int n = ncol + nt * 8;
                        float v0 = acc[mt][nt][2 * h];
                        float v1 = acc[mt][nt][2 * h + 1];
                        if (n < K)     { logits[base + n] = v0;     rmax = fmaxf(rmax, v0); }
                        if (n + 1 < K) { logits[base + n + 1] = v1; rmax = fmaxf(rmax, v1); }
                    }
                    rmax = fmaxf(rmax, __shfl_xor_sync(0xFFFFFFFFu, rmax, 1));
                    rmax = fmaxf(rmax, __shfl_xor_sync(0xFFFFFFFFu, rmax, 2));
                    if ((lane & 3) == 0)
                        atomicMax(&g_rowmax_u[gr], f2mono(rmax));
                }
            }
        }
        __syncthreads();   // all warps done reading buf (m&1) before iter m+1 prefetch reuses it
    }
}

// ---------------------------------------------------------------------------
// single-pass thresholded logsumexp using precomputed row max
// ---------------------------------------------------------------------------
__global__ void lse_kernel(const float* __restrict__ logits, int B, int K) {
    int b = blockIdx.x;
    if (b >= B) return;
    const float* row = logits + (size_t)b * K;
    int tid = threadIdx.x;
    __shared__ float sm[256];

    float m = mono2f(g_rowmax_u[b]);
    float thr = m - 30.0f;
    float s = 0.0f;
    for (int i = tid; i < K; i += 256) {
        float v = row[i];
        if (v > thr) s += expf(v - m);
    }
    sm[tid] = s;
    __syncthreads();
    for (int k = 128; k > 0; k >>= 1) {
        if (tid < k) sm[tid] += sm[tid + k];
        __syncthreads();
    }
    if (tid == 0) {
        float lse = m + logf(sm[0]);
        g_row_loss[b] = lse - row[g_y32[b]];
    }
}

__global__ void loss_kernel(float* __restrict__ out, int B) {
    __shared__ float sm[256];
    int tid = threadIdx.x;
    float s = 0.0f;
    for (int i = tid; i < B; i += 256) s += g_row_loss[i];
    sm[tid] = s;
    __syncthreads();
    for (int k = 128; k > 0; k >>= 1) {
        if (tid < k) sm[tid] += sm[tid + k];
        __syncthreads();
    }
    if (tid == 0) out[0] = sm[0] / (float)B;
}

// ---------------------------------------------------------------------------
// launch — inputs identified by element count
// ---------------------------------------------------------------------------
extern "C" void kernel_launch(void* const* d_in, const int* in_sizes, int n_in,
                              void* d_out, int out_size) {
    int order[16];
    for (int i = 0; i < n_in; ++i) order[i] = i;
    for (int i = 0; i < n_in; ++i)
        for (int j = i + 1; j < n_in; ++j)
            if (in_sizes[order[j]] > in_sizes[order[i]]) {
                int t = order[i]; order[i] = order[j]; order[j] = t;
            }
    const float* weights  = (const float*)d_in[order[0]];
    const void*  pi_p     = d_in[order[1]];
    const float* x        = (const float*)d_in[order[2]];
    const int*   path_len = (const int*)d_in[order[3]];
    const void*  y_p      = d_in[order[4]];

    const int pi_n = in_sizes[order[1]];
    const int K    = in_sizes[order[3]];
    const int B    = in_sizes[order[4]];
    const int Dmax = pi_n / K;

    const int ntiles = (K + 127) / 128;
    const int mtiles = (B + 127) / 128;

    float* out    = (float*)d_out;
    float* loss   = out;
    float* logits = out + 1;
    float* aw     = out + 1 + (size_t)B * K;

    cudaFuncSetAttribute(gemm_kernel, cudaFuncAttributeMaxDynamicSharedMemorySize, SMEM_TOTAL);

    init_kernel<<<(B + 255) / 256, 256>>>(B);
    detect_kernel<<<1, 32>>>((const unsigned int*)pi_p);
    int nconv = pi_n > B ? pi_n : B;
    convert_kernel<<<(nconv + 255) / 256, 256>>>(pi_p, y_p, pi_n, B);

    xconv_kernel<<<mtiles * 128, 128>>>(x, B);
    aw_kernel<<<ntiles * 128, 128>>>(weights, path_len, aw, K, Dmax);

    gemm_kernel<<<ntiles, 256, SMEM_TOTAL>>>(logits, B, K, mtiles);

    lse_kernel<<<B, 256>>>(logits, B, K);
    loss_kernel<<<1, 256>>>(loss, B);
}